// round 7
// baseline (speedup 1.0000x reference)
#include <cuda_runtime.h>
#include <cuda_bf16.h>
#include <math.h>
#include <stdint.h>

#define E_DIM 1024
#define BATCH 4
#define SEQ 2048
#define M_TOT (BATCH * SEQ)   // 8192

// ---------------- scratch (allocation-free: __device__ globals) -------------
// packed pair format: uint2 = [hi bf16x2 of (2k,2k+1), lo bf16x2]
__device__ uint2 g_xpk [(size_t)M_TOT * (E_DIM / 2)];          // 32 MB
__device__ uint2 g_wqpk[(size_t)3 * E_DIM * (E_DIM / 2)];      // 12 MB
__device__ uint2 g_wopk[(size_t)E_DIM * (E_DIM / 2)];          // 4 MB
__device__ uint2 g_gwpk[(size_t)E_DIM * (E_DIM / 2)];          // 4 MB
__device__ uint2 g_qpk [(size_t)M_TOT * (E_DIM / 2)];          // 32 MB (scaled q)
__device__ uint2 g_kpk [(size_t)M_TOT * (E_DIM / 2)];          // 32 MB
__device__ uint2 g_vt  [(size_t)BATCH * E_DIM * (SEQ / 2)];    // 32 MB (V^T)
__device__ float g_scores[(size_t)BATCH * SEQ * SEQ];          // 64 MB
__device__ uint2 g_atpk[(size_t)M_TOT * (SEQ / 2)];            // 64 MB
__device__ uint2 g_aopk[(size_t)M_TOT * (E_DIM / 2)];          // 32 MB
__device__ uint2 g_oopk[(size_t)M_TOT * (E_DIM / 2)];          // 32 MB
__device__ float g_oof [(size_t)M_TOT * E_DIM];                // 32 MB

// ---------------- smem geometry ----------------------------------------------
// per 32-k chunk per operand: 128 rows x 16 pairs (8B) = 128B data, pad to 160B
#define RS 160
#define TILE_BYTES (128 * RS)       // 20480
#define STAGE (2 * TILE_BYTES)      // 40960
#define SMEM_BYTES (2 * STAGE)      // 81920 (also >= 128*132*4 transpose buf)

// ---------------- helpers -----------------------------------------------------
__device__ __forceinline__ uint32_t pack_bf(float lo, float hi) {
    uint32_t w;
    asm("cvt.rn.bf16x2.f32 %0, %1, %2;" : "=r"(w) : "f"(hi), "f"(lo));
    return w;
}

// split (x,y) into bf16 hi pair + bf16 residual pair
__device__ __forceinline__ uint2 pk2(float x, float y) {
    uint32_t h = pack_bf(x, y);
    float hx = __uint_as_float(h << 16);
    float hy = __uint_as_float(h & 0xffff0000u);
    uint32_t l = pack_bf(x - hx, y - hy);
    return make_uint2(h, l);
}

__device__ __forceinline__ void lds2(uint32_t& a, uint32_t& b, uint32_t addr) {
    asm volatile("ld.shared.v2.b32 {%0, %1}, [%2];" : "=r"(a), "=r"(b) : "r"(addr));
}

__device__ __forceinline__ void mma16(float c[4], const uint32_t a[4], const uint32_t b[2]) {
    asm volatile(
        "mma.sync.aligned.m16n8k16.row.col.f32.bf16.bf16.f32 "
        "{%0,%1,%2,%3}, {%4,%5,%6,%7}, {%8,%9}, {%0,%1,%2,%3};"
        : "+f"(c[0]), "+f"(c[1]), "+f"(c[2]), "+f"(c[3])
        : "r"(a[0]), "r"(a[1]), "r"(a[2]), "r"(a[3]), "r"(b[0]), "r"(b[1]));
}

__device__ __forceinline__ void cpa16(uint32_t dst, const void* src) {
    asm volatile("cp.async.cg.shared.global [%0], [%1], 16;" :: "r"(dst), "l"(src));
}
#define CP_COMMIT() asm volatile("cp.async.commit_group;")
#define CP_WAIT(n)  asm volatile("cp.async.wait_group %0;" :: "n"(n))

// stage one 128-row x 16-pair tile (1024 16B chunks, 4 per thread)
__device__ __forceinline__ void stage_tile(uint32_t sdst, const uint2* __restrict__ g,
                                           int ldP, int kp0, int tid) {
    #pragma unroll
    for (int i = 0; i < 4; i++) {
        const int idx = tid + i * 256;
        const int row = idx >> 3;
        const int ch  = idx & 7;
        cpa16(sdst + row * RS + ch * 16, g + (long)row * ldP + kp0 + ch * 2);
    }
}

// ---------------- packed bf16x3 tensor-core GEMM (all NT) --------------------
// C(M,N) = A @ B^T with A (M rows, Kpairs) packed, B (N rows, Kpairs) packed.
// EPI 0: Cf fp32.            EPI 1: Cp packed.
// EPI 2: Cp packed + Cf fp32. EPI 3: Cf = Comp * sigmoid(acc).
// EPI 4: QKV special — bn<1024: q (scale 1/8) -> Cp; bn<2048: k -> Pk;
//        else: V^T transpose -> Pvt.
template <int EPI>
__global__ __launch_bounds__(256, 2)
void mm_pk(const uint2* __restrict__ A, const uint2* __restrict__ B,
           int Kpairs, int ldaP, int ldbP,
           float* __restrict__ Cf, int ldc,
           uint2* __restrict__ Cp, int ldcP,
           const float* __restrict__ Comp,
           uint2* __restrict__ Pk, uint2* __restrict__ Pvt,
           long bsA, long bsB, long bsCf, long bsCp)
{
    extern __shared__ char smem[];
    A  += (long)blockIdx.z * bsA;
    B  += (long)blockIdx.z * bsB;
    if (EPI == 0 || EPI == 2 || EPI == 3) Cf += (long)blockIdx.z * bsCf;
    if (EPI == 1 || EPI == 2)             Cp += (long)blockIdx.z * bsCp;

    const int tid  = threadIdx.x;
    const int lane = tid & 31;
    const int wid  = tid >> 5;
    const int g    = lane >> 2;
    const int tig  = lane & 3;
    const int bm = blockIdx.y * 128;
    const int bn = blockIdx.x * 128;
    const int wm = (wid & 1) * 64;
    const int wn = (wid >> 1) * 32;

    const uint32_t sbase = (uint32_t)__cvta_generic_to_shared(smem);
    const uint2* Ab = A + (long)bm * ldaP;
    const uint2* Bb = B + (long)bn * ldbP;

    float acc[4][4][4];
    #pragma unroll
    for (int mt = 0; mt < 4; mt++)
        #pragma unroll
        for (int nt = 0; nt < 4; nt++)
            #pragma unroll
            for (int i = 0; i < 4; i++) acc[mt][nt][i] = 0.f;

    const int NC = Kpairs >> 4;

    stage_tile(sbase, Ab, ldaP, 0, tid);
    stage_tile(sbase + TILE_BYTES, Bb, ldbP, 0, tid);
    CP_COMMIT();

    for (int c = 0; c < NC; c++) {
        if (c + 1 < NC) {
            const uint32_t st = sbase + ((c + 1) & 1) * STAGE;
            stage_tile(st, Ab, ldaP, (c + 1) << 4, tid);
            stage_tile(st + TILE_BYTES, Bb, ldbP, (c + 1) << 4, tid);
            CP_COMMIT();
            CP_WAIT(1);
        } else {
            CP_WAIT(0);
        }
        __syncthreads();

        const uint32_t ab = sbase + (c & 1) * STAGE;
        const uint32_t bb = ab + TILE_BYTES;
        #pragma unroll
        for (int s = 0; s < 2; s++) {
            const int po = s * 8;
            uint32_t ah[4][4], al[4][4], bh[4][2], bl[4][2];
            #pragma unroll
            for (int mt = 0; mt < 4; mt++) {
                const uint32_t base = ab + (wm + mt * 16 + g) * RS + (po + tig) * 8;
                lds2(ah[mt][0], al[mt][0], base);
                lds2(ah[mt][1], al[mt][1], base + 8 * RS);
                lds2(ah[mt][2], al[mt][2], base + 32);
                lds2(ah[mt][3], al[mt][3], base + 8 * RS + 32);
            }
            #pragma unroll
            for (int nt = 0; nt < 4; nt++) {
                const uint32_t nb = bb + (wn + nt * 8 + g) * RS + (po + tig) * 8;
                lds2(bh[nt][0], bl[nt][0], nb);
                lds2(bh[nt][1], bl[nt][1], nb + 32);
            }
            #pragma unroll
            for (int mt = 0; mt < 4; mt++)
                #pragma unroll
                for (int nt = 0; nt < 4; nt++) {
                    mma16(acc[mt][nt], ah[mt], bh[nt]);
                    mma16(acc[mt][nt], ah[mt], bl[nt]);
                    mma16(acc[mt][nt], al[mt], bh[nt]);
                }
        }
        __syncthreads();
    }

    // ---- epilogues ----
    if (EPI == 4 && bn >= 2048) {
        // V tile: transpose via smem, emit packed V^T
        float* ts = (float*)smem;
        #pragma unroll
        for (int mt = 0; mt < 4; mt++)
            #pragma unroll
            for (int nt = 0; nt < 4; nt++) {
                const int r  = wm + mt * 16 + g;
                const int cc = wn + nt * 8 + 2 * tig;
                ts[r * 132 + cc]           = acc[mt][nt][0];
                ts[r * 132 + cc + 1]       = acc[mt][nt][1];
                ts[(r + 8) * 132 + cc]     = acc[mt][nt][2];
                ts[(r + 8) * 132 + cc + 1] = acc[mt][nt][3];
            }
        __syncthreads();
        const int nl = tid >> 1;          // 0..127 (local feature col)
        const int mh = tid & 1;           // half of the 64 m-pairs
        const int b  = bm >> 11;
        uint2* dst = Pvt + (long)b * (E_DIM * (SEQ / 2))
                         + (long)(bn - 2048 + nl) * (SEQ / 2)
                         + ((bm & 2047) >> 1) + mh * 32;
        #pragma unroll
        for (int p = 0; p < 32; p++) {
            const int m2 = (mh * 32 + p) * 2;
            dst[p] = pk2(ts[m2 * 132 + nl], ts[(m2 + 1) * 132 + nl]);
        }
        return;
    }

    #pragma unroll
    for (int mt = 0; mt < 4; mt++) {
        #pragma unroll
        for (int nt = 0; nt < 4; nt++) {
            const long r  = bm + wm + mt * 16 + g;
            const int  cl = wn + nt * 8 + 2 * tig;
            float v0 = acc[mt][nt][0], v1 = acc[mt][nt][1];
            float v2 = acc[mt][nt][2], v3 = acc[mt][nt][3];
            if (EPI == 0) {
                const long cc = bn + cl;
                *(float2*)&Cf[r * ldc + cc]       = make_float2(v0, v1);
                *(float2*)&Cf[(r + 8) * ldc + cc] = make_float2(v2, v3);
            } else if (EPI == 1 || EPI == 2) {
                const long cp = (bn + cl) >> 1;
                Cp[r * ldcP + cp]       = pk2(v0, v1);
                Cp[(r + 8) * ldcP + cp] = pk2(v2, v3);
                if (EPI == 2) {
                    const long cc = bn + cl;
                    *(float2*)&Cf[r * ldc + cc]       = make_float2(v0, v1);
                    *(float2*)&Cf[(r + 8) * ldc + cc] = make_float2(v2, v3);
                }
            } else if (EPI == 3) {
                const long cc = bn + cl;
                float2 o0 = *(const float2*)&Comp[r * ldc + cc];
                float2 o1 = *(const float2*)&Comp[(r + 8) * ldc + cc];
                v0 = o0.x / (1.f + expf(-v0));
                v1 = o0.y / (1.f + expf(-v1));
                v2 = o1.x / (1.f + expf(-v2));
                v3 = o1.y / (1.f + expf(-v3));
                *(float2*)&Cf[r * ldc + cc]       = make_float2(v0, v1);
                *(float2*)&Cf[(r + 8) * ldc + cc] = make_float2(v2, v3);
            } else if (EPI == 4) {
                // q or k region
                uint2* dst = (bn < 1024) ? Cp : Pk;
                const int cb = (bn < 1024) ? bn : bn - 1024;
                const float sc = (bn < 1024) ? 0.125f : 1.0f;
                const long cp = (long)((cb + cl) >> 1);
                dst[r * 512 + cp]       = pk2(sc * v0, sc * v1);
                dst[(r + 8) * 512 + cp] = pk2(sc * v2, sc * v3);
            }
        }
    }
}

// ---------------- pack fp32 -> hi/lo pair format ------------------------------
__global__ __launch_bounds__(256)
void pack_arr(const float* __restrict__ s, uint2* __restrict__ d, int npairs)
{
    const int i = blockIdx.x * 256 + threadIdx.x;
    if (i < npairs) {
        float2 v = ((const float2*)s)[i];
        d[i] = pk2(v.x, v.y);
    }
}

// ---------------- row softmax (fp32 in, packed out) --------------------------
__global__ __launch_bounds__(256)
void softmax_pack(const float* __restrict__ scores, uint2* __restrict__ attn)
{
    const float4* row = (const float4*)(scores + (size_t)blockIdx.x * SEQ);
    uint2* drow = attn + (size_t)blockIdx.x * (SEQ / 2);
    const int tid = threadIdx.x;
    __shared__ float red[8];

    float4 v0 = row[tid];
    float4 v1 = row[tid + 256];

    float m = fmaxf(fmaxf(fmaxf(v0.x, v0.y), fmaxf(v0.z, v0.w)),
                    fmaxf(fmaxf(v1.x, v1.y), fmaxf(v1.z, v1.w)));
    #pragma unroll
    for (int o = 16; o > 0; o >>= 1) m = fmaxf(m, __shfl_xor_sync(0xffffffffu, m, o));
    if ((tid & 31) == 0) red[tid >> 5] = m;
    __syncthreads();
    float bm = red[0];
    #pragma unroll
    for (int i = 1; i < 8; i++) bm = fmaxf(bm, red[i]);
    __syncthreads();

    v0.x = expf(v0.x - bm); v0.y = expf(v0.y - bm);
    v0.z = expf(v0.z - bm); v0.w = expf(v0.w - bm);
    v1.x = expf(v1.x - bm); v1.y = expf(v1.y - bm);
    v1.z = expf(v1.z - bm); v1.w = expf(v1.w - bm);

    float s = v0.x + v0.y + v0.z + v0.w + v1.x + v1.y + v1.z + v1.w;
    #pragma unroll
    for (int o = 16; o > 0; o >>= 1) s += __shfl_xor_sync(0xffffffffu, s, o);
    if ((tid & 31) == 0) red[tid >> 5] = s;
    __syncthreads();
    float tot = 0.f;
    #pragma unroll
    for (int i = 0; i < 8; i++) tot += red[i];
    const float inv = 1.0f / tot;

    v0.x *= inv; v0.y *= inv; v0.z *= inv; v0.w *= inv;
    v1.x *= inv; v1.y *= inv; v1.z *= inv; v1.w *= inv;

    uint2 p0 = pk2(v0.x, v0.y), p1 = pk2(v0.z, v0.w);
    *(uint4*)&drow[2 * tid] = make_uint4(p0.x, p0.y, p1.x, p1.y);
    p0 = pk2(v1.x, v1.y); p1 = pk2(v1.z, v1.w);
    *(uint4*)&drow[512 + 2 * tid] = make_uint4(p0.x, p0.y, p1.x, p1.y);
}

// ---------------- launch -----------------------------------------------------
extern "C" void kernel_launch(void* const* d_in, const int* in_sizes, int n_in,
                              void* d_out, int out_size)
{
    const float* w_qkv = (const float*)d_in[0];  // (3E, E)
    const float* w_out = (const float*)d_in[1];  // (E, E)
    const float* x     = (const float*)d_in[2];  // (B, S, E)
    const float* g_w   = (const float*)d_in[3];  // (E, E)
    float* out = (float*)d_out;                  // (B, S, E)

    uint2 *xpk, *wqpk, *wopk, *gwpk, *qpk, *kpk, *vt, *atpk, *aopk, *oopk;
    float *sc, *oof;
    cudaGetSymbolAddress((void**)&xpk,  g_xpk);
    cudaGetSymbolAddress((void**)&wqpk, g_wqpk);
    cudaGetSymbolAddress((void**)&wopk, g_wopk);
    cudaGetSymbolAddress((void**)&gwpk, g_gwpk);
    cudaGetSymbolAddress((void**)&qpk,  g_qpk);
    cudaGetSymbolAddress((void**)&kpk,  g_kpk);
    cudaGetSymbolAddress((void**)&vt,   g_vt);
    cudaGetSymbolAddress((void**)&sc,   g_scores);
    cudaGetSymbolAddress((void**)&atpk, g_atpk);
    cudaGetSymbolAddress((void**)&aopk, g_aopk);
    cudaGetSymbolAddress((void**)&oopk, g_oopk);
    cudaGetSymbolAddress((void**)&oof,  g_oof);

    cudaFuncSetAttribute(mm_pk<0>, cudaFuncAttributeMaxDynamicSharedMemorySize, SMEM_BYTES);
    cudaFuncSetAttribute(mm_pk<1>, cudaFuncAttributeMaxDynamicSharedMemorySize, SMEM_BYTES);
    cudaFuncSetAttribute(mm_pk<2>, cudaFuncAttributeMaxDynamicSharedMemorySize, SMEM_BYTES);
    cudaFuncSetAttribute(mm_pk<3>, cudaFuncAttributeMaxDynamicSharedMemorySize, SMEM_BYTES);
    cudaFuncSetAttribute(mm_pk<4>, cudaFuncAttributeMaxDynamicSharedMemorySize, SMEM_BYTES);

    // 0) pack weights + input
    pack_arr<<<(M_TOT * E_DIM / 2 + 255) / 256, 256>>>(x, xpk, M_TOT * E_DIM / 2);
    pack_arr<<<(3 * E_DIM * E_DIM / 2 + 255) / 256, 256>>>(w_qkv, wqpk, 3 * E_DIM * E_DIM / 2);
    pack_arr<<<(E_DIM * E_DIM / 2 + 255) / 256, 256>>>(w_out, wopk, E_DIM * E_DIM / 2);
    pack_arr<<<(E_DIM * E_DIM / 2 + 255) / 256, 256>>>(g_w, gwpk, E_DIM * E_DIM / 2);

    // 1) qkv projection -> packed q (scaled), k, V^T
    mm_pk<4><<<dim3(24, 64, 1), 256, SMEM_BYTES>>>(
        xpk, wqpk, E_DIM / 2, E_DIM / 2, E_DIM / 2,
        nullptr, 0, qpk, 512, nullptr, kpk, vt, 0, 0, 0, 0);

    // 2) scores = (q/8) @ k^T -> fp32, batched
    mm_pk<0><<<dim3(16, 16, BATCH), 256, SMEM_BYTES>>>(
        qpk, kpk, E_DIM / 2, E_DIM / 2, E_DIM / 2,
        sc, SEQ, nullptr, 0, nullptr, nullptr, nullptr,
        (long)SEQ * (E_DIM / 2), (long)SEQ * (E_DIM / 2), (long)SEQ * SEQ, 0);

    // 3) softmax -> packed attn
    softmax_pack<<<M_TOT, 256>>>(sc, atpk);

    // 4) attn_out = attn @ (V^T)^T -> packed, batched
    mm_pk<1><<<dim3(8, 16, BATCH), 256, SMEM_BYTES>>>(
        atpk, vt, SEQ / 2, SEQ / 2, SEQ / 2,
        nullptr, 0, aopk, E_DIM / 2, nullptr, nullptr, nullptr,
        (long)SEQ * (SEQ / 2), (long)E_DIM * (SEQ / 2), 0, (long)SEQ * (E_DIM / 2));

    // 5) out = attn_out @ w_out^T -> packed + fp32
    mm_pk<2><<<dim3(8, 64, 1), 256, SMEM_BYTES>>>(
        aopk, wopk, E_DIM / 2, E_DIM / 2, E_DIM / 2,
        oof, E_DIM, oopk, E_DIM / 2, nullptr, nullptr, nullptr, 0, 0, 0, 0);

    // 6) final = out * sigmoid(out @ gate_w^T)
    mm_pk<3><<<dim3(8, 64, 1), 256, SMEM_BYTES>>>(
        oopk, gwpk, E_DIM / 2, E_DIM / 2, E_DIM / 2,
        out, E_DIM, nullptr, 0, oof, nullptr, nullptr, 0, 0, 0, 0);
}